// round 17
// baseline (speedup 1.0000x reference)
#include <cuda_runtime.h>
#include <cuda_bf16.h>
#include <cuda_fp16.h>
#include <stdint.h>

#define N_AGENTS 16384
#define OBS_DIM  2048
#define HID      512

// ---- enc GEMM tiling: BM=64, BN=256, KC=64, 256 threads, occ 2,
//      1-term fp16, fused x conversion, fused head tail ----
#define KC 64
#define NCHUNK (OBS_DIM / KC)    // 32
#define MT64  (N_AGENTS / 64)    // 256 m-tiles of 64 rows
#define MTILES (N_AGENTS / 128)  // 128 head tiles

// enc smem (bytes): A32 2x16K @0 ; A16 2x8K @32768 ; B 2x32K @49152 ; bias @114688
// head phase reuse: W' 64K @0 ; A ring 4x8K @65536 ; logits @0
#define A32_OFF 0
#define A16_OFF 32768
#define EB_OFF  49152
#define EBIAS_OFF 114688
#define ENC_SMEM 115712
#define HB_OFF 0
#define HA_OFF 65536

// B: pre-converted single fp16, [tile128][chunk][16K]
__device__ __align__(1024) unsigned char g_Bstage[(size_t)4 * NCHUNK * 16384];
// hidden: single fp16 plane head tiles: [mtile128][hchunk 0..7][16K]
__device__ __align__(1024) unsigned char g_Ahead[(size_t)MTILES * 8 * 16384];
// W' = [Ws(32); Wc(1); 0(31)] single fp16: [chunk 0..7][8K]
__device__ __align__(1024) unsigned char g_Whead[(size_t)8 * 8192];
// per-mt64 arrival counters (zeroed in conv_wh each launch)
__device__ int g_cnt[MT64];

static __device__ __forceinline__ uint32_t smem_addr_u32(const void* p) {
    uint32_t a;
    asm("{ .reg .u64 t; cvta.to.shared.u64 t, %1; cvt.u32.u64 %0, t; }" : "=r"(a) : "l"(p));
    return a;
}

static __device__ __forceinline__ void ldm_x4(uint32_t* r, uint32_t addr) {
    asm volatile("ldmatrix.sync.aligned.m8n8.x4.shared.b16 {%0,%1,%2,%3}, [%4];"
                 : "=r"(r[0]), "=r"(r[1]), "=r"(r[2]), "=r"(r[3]) : "r"(addr));
}

static __device__ __forceinline__ void mma_f16(float* c, const uint32_t* a,
                                               const uint32_t* b) {
    asm volatile(
        "mma.sync.aligned.m16n8k16.row.col.f32.f16.f16.f32 "
        "{%0,%1,%2,%3}, {%4,%5,%6,%7}, {%8,%9}, {%0,%1,%2,%3};"
        : "+f"(c[0]), "+f"(c[1]), "+f"(c[2]), "+f"(c[3])
        : "r"(a[0]), "r"(a[1]), "r"(a[2]), "r"(a[3]), "r"(b[0]), "r"(b[1]));
}

static __device__ __forceinline__ uint32_t packh2(float x0, float x1) {
    __half2 hp;
    hp.x = __float2half_rn(x0);
    hp.y = __float2half_rn(x1);
    return *(uint32_t*)&hp;
}

// ---------------------------------------------------------------------------
// conv (W_enc): fp32 -> single fp16 plane, pre-swizzled. (proven)
// ---------------------------------------------------------------------------
__global__ void conv_f16_kernel(const float* __restrict__ S, unsigned char* __restrict__ D) {
    const int gid = blockIdx.x * 256 + threadIdx.x;
    const int n   = gid >> 8;
    const int k0  = (gid & 255) << 3;
    const float* src = S + (size_t)n * OBS_DIM + k0;
    float4 v0 = *(const float4*)src;
    float4 v1 = *(const float4*)(src + 4);

    uint32_t hv[4];
    hv[0] = packh2(v0.x, v0.y);
    hv[1] = packh2(v0.z, v0.w);
    hv[2] = packh2(v1.x, v1.y);
    hv[3] = packh2(v1.z, v1.w);

    const int c  = k0 >> 6;
    const int kl = k0 & 63;
    const int t  = n >> 7;
    const int nl = n & 127;
    const uint32_t byte = (uint32_t)nl * 128 +
                          (((uint32_t)kl * 2) ^ ((uint32_t)(nl & 7) << 4));
    unsigned char* blk = D + ((size_t)(t * NCHUNK + c)) * 16384;
    *(uint4*)(blk + byte) = make_uint4(hv[0], hv[1], hv[2], hv[3]);
}

// ---------------------------------------------------------------------------
// conv W' + zero g_cnt. (proven; counters added)
// ---------------------------------------------------------------------------
__global__ void conv_wh_kernel(const float* __restrict__ Ws, const float* __restrict__ Wc) {
    const int u   = blockIdx.x * 256 + threadIdx.x;   // 0..4095
    if (u < MT64) g_cnt[u] = 0;
    const int row = u >> 6;
    const int k0  = (u & 63) << 3;
    float f[8];
    if (row < 32) {
        const float4* s4 = (const float4*)(Ws + (size_t)row * HID + k0);
        *(float4*)(f) = s4[0];
        *(float4*)(f + 4) = s4[1];
    } else if (row == 32) {
        const float4* s4 = (const float4*)(Wc + k0);
        *(float4*)(f) = s4[0];
        *(float4*)(f + 4) = s4[1];
    } else {
#pragma unroll
        for (int e = 0; e < 8; e++) f[e] = 0.f;
    }
    uint32_t hv[4];
#pragma unroll
    for (int j = 0; j < 4; j++) hv[j] = packh2(f[2 * j], f[2 * j + 1]);
    const int c  = k0 >> 6;
    const int kl = k0 & 63;
    const uint32_t byte = (uint32_t)row * 128 +
                          (((uint32_t)kl * 2) ^ ((uint32_t)(row & 7) << 4));
    *(uint4*)(g_Whead + (size_t)c * 8192 + byte) = make_uint4(hv[0], hv[1], hv[2], hv[3]);
}

// ---------------------------------------------------------------------------
// Fused enc GEMM + head tail. Enc part = R16-proven schedule.
// After epilogue: atomic handoff; second arriver per mt64 runs head v3 body.
// ---------------------------------------------------------------------------
__global__ __launch_bounds__(256, 2) void enc_gemm_mma(
    const float* __restrict__ X, const float* __restrict__ bias,
    const float* __restrict__ bs, const float* __restrict__ bc,
    const int* __restrict__ skill, const int* __restrict__ action,
    float* __restrict__ out)
{
    extern __shared__ __align__(1024) unsigned char smem[];
    __shared__ int s_old;
    const int tid = threadIdx.x;
    const int w = tid >> 5, l = tid & 31;
    const int mt64  = blockIdx.x >> 1;
    const int ntile = blockIdx.x & 1;
    const int m0 = mt64 * 64;
    const int n0 = ntile * 256;
    const uint32_t sb = smem_addr_u32(smem);
    float* bsm = (float*)(smem + EBIAS_OFF);
    bsm[tid] = bias[n0 + tid];

    const float* gX = X + (size_t)m0 * OBS_DIM;
    const unsigned char* gB0 = g_Bstage + (size_t)(ntile * 2) * NCHUNK * 16384;
    const unsigned char* gB1 = g_Bstage + (size_t)(ntile * 2 + 1) * NCHUNK * 16384;

    float acc[4][4][4];
#pragma unroll
    for (int i = 0; i < 4; i++)
#pragma unroll
        for (int j = 0; j < 4; j++)
#pragma unroll
            for (int q = 0; q < 4; q++) acc[i][j][q] = 0.f;

    const int wn = w * 32;
    const int idx = l & 7, seg = l >> 3;
    const int arl = idx + (seg & 1) * 8;
    const int acb = (seg >> 1) * 16;
    const int brl = idx + (seg >> 1) * 8;
    const int bkb = (seg & 1) * 16;
    const uint32_t sxor = (uint32_t)idx << 4;

#define EISSUE_A(k)                                                             \
    {                                                                           \
        const uint32_t dstA = sb + A32_OFF + ((k) & 1) * 16384;                 \
        _Pragma("unroll") for (int i = 0; i < 4; i++) {                         \
            const int blk = i * 256 + tid;                                      \
            const float* gsrc = gX + (size_t)(blk >> 4) * OBS_DIM +             \
                                (k) * KC + (blk & 15) * 4;                      \
            asm volatile("cp.async.cg.shared.global [%0], [%1], 16;"            \
                         :: "r"(dstA + (uint32_t)blk * 16), "l"(gsrc) : "memory"); \
        }                                                                       \
    }

#define EISSUE_B(k)                                                             \
    {                                                                           \
        const uint32_t dstB = sb + EB_OFF + ((k) & 1) * 32768;                  \
        const unsigned char* gb0 = gB0 + (size_t)(k) * 16384;                   \
        const unsigned char* gb1 = gB1 + (size_t)(k) * 16384;                   \
        _Pragma("unroll") for (int i = 0; i < 4; i++) {                         \
            uint32_t off = (uint32_t)(i * 256 + tid) * 16;                      \
            asm volatile("cp.async.cg.shared.global [%0], [%1], 16;"            \
                         :: "r"(dstB + off), "l"(gb0 + off) : "memory");        \
            asm volatile("cp.async.cg.shared.global [%0], [%1], 16;"            \
                         :: "r"(dstB + 16384 + off), "l"(gb1 + off) : "memory"); \
        }                                                                       \
    }

#define ECOMMIT() asm volatile("cp.async.commit_group;" ::: "memory")

#define ECONVERT(k)                                                             \
    {                                                                           \
        const unsigned char* a32 = smem + A32_OFF + ((k) & 1) * 16384;          \
        unsigned char* a16 = smem + A16_OFF + ((k) & 1) * 8192;                 \
        _Pragma("unroll") for (int i = 0; i < 4; i++) {                         \
            const int blk = i * 256 + tid;                                      \
            float4 v = *(const float4*)(a32 + (size_t)blk * 16);                \
            uint32_t h0 = packh2(v.x, v.y);                                     \
            uint32_t h1 = packh2(v.z, v.w);                                     \
            const int row = blk >> 4;                                           \
            const uint32_t kb = (uint32_t)(blk & 15) * 8;                       \
            const uint32_t swo = (uint32_t)row * 128 +                          \
                                 (kb ^ ((uint32_t)(row & 7) << 4));             \
            *(uint2*)(a16 + swo) = make_uint2(h0, h1);                          \
        }                                                                       \
    }

    // prologue (R16-proven): convert(0) before A(2) aliases slot 0
    EISSUE_A(0); EISSUE_A(1); EISSUE_B(0); ECOMMIT();
    asm volatile("cp.async.wait_group 0;" ::: "memory");
    ECONVERT(0);
    EISSUE_A(2); EISSUE_B(1); ECOMMIT();

    for (int c = 0; c < NCHUNK; c++) {
        if (c < NCHUNK - 1) {
            asm volatile("cp.async.wait_group 1;" ::: "memory");
        } else {
            asm volatile("cp.async.wait_group 0;" ::: "memory");
        }
        __syncthreads();

        const uint32_t stA = sb + A16_OFF + (c & 1) * 8192;
        const uint32_t stB = sb + EB_OFF + (c & 1) * 32768;

#pragma unroll
        for (int ks = 0; ks < 4; ks++) {
            const int kb = ks * 32;
            uint32_t a[4][4], b[8];
#pragma unroll
            for (int mt = 0; mt < 4; mt++) {
                uint32_t off = (uint32_t)(mt * 16 + arl) * 128 +
                               (((uint32_t)(kb + acb)) ^ sxor);
                ldm_x4(a[mt], stA + off);
            }
#pragma unroll
            for (int g = 0; g < 2; g++) {
                uint32_t off = (uint32_t)(wn + g * 16 + brl) * 128 +
                               (((uint32_t)(kb + bkb)) ^ sxor);
                ldm_x4(&b[g * 4], stB + off);
            }
#pragma unroll
            for (int mt = 0; mt < 4; mt++)
#pragma unroll
                for (int nt = 0; nt < 4; nt++)
                    mma_f16(acc[mt][nt], a[mt], &b[nt * 2]);
        }

        if (c + 1 < NCHUNK) ECONVERT(c + 1);

        __syncthreads();

        const bool iA = (c + 3 < NCHUNK);
        const bool iB = (c + 2 < NCHUNK);
        if (iA) EISSUE_A(c + 3);
        if (iB) EISSUE_B(c + 2);
        if (iA || iB) ECOMMIT();
    }

    // enc epilogue: bias + relu, write fp16 head tiles
    unsigned char* gAh = g_Ahead + (size_t)(mt64 >> 1) * 8 * 16384;
    const int rbase = (mt64 & 1) * 64;
#pragma unroll
    for (int mt = 0; mt < 4; mt++)
#pragma unroll
        for (int nt = 0; nt < 4; nt++) {
            const int colL = wn + nt * 8 + (l & 3) * 2;
            const float b0 = bsm[colL], b1 = bsm[colL + 1];
            const int r0 = rbase + mt * 16 + (l >> 2);
            const int n = n0 + colL;
            const int cch = n >> 6;
            const int kc = n & 63;
            unsigned char* blk = gAh + (size_t)cch * 16384;

            const uint32_t h01 = packh2(fmaxf(acc[mt][nt][0] + b0, 0.f),
                                        fmaxf(acc[mt][nt][1] + b1, 0.f));
            const uint32_t h23 = packh2(fmaxf(acc[mt][nt][2] + b0, 0.f),
                                        fmaxf(acc[mt][nt][3] + b1, 0.f));

            const uint32_t by0 = (uint32_t)r0 * 128 +
                                 (((uint32_t)(2 * kc)) ^ ((uint32_t)(r0 & 7) << 4));
            const int r1 = r0 + 8;
            const uint32_t by1 = (uint32_t)r1 * 128 +
                                 (((uint32_t)(2 * kc)) ^ ((uint32_t)(r1 & 7) << 4));
            *(uint32_t*)(blk + by0) = h01;
            *(uint32_t*)(blk + by1) = h23;
        }

    // ---- atomic handoff: second arriver per mt64 runs the head phase ----
    __threadfence();
    __syncthreads();             // all epilogue stores issued before fence+add
    if (tid == 0) s_old = atomicAdd(&g_cnt[mt64], 1);
    __syncthreads();
    if (s_old == 0) return;      // first arriver exits
    __threadfence();             // acquire: partner's g_Ahead writes visible

    // ================= head phase (head v3 body, proven) =================
    {
        const int mtile = mt64 >> 1;
        const int mhalf = mt64 & 1;
        const unsigned char* gA = g_Ahead + (size_t)mtile * 8 * 16384 + mhalf * 8192;

        {
            const uint32_t dst = sb + HB_OFF;
#pragma unroll
            for (int i = 0; i < 16; i++) {
                uint32_t off = (uint32_t)(i * 256 + tid) * 16;
                asm volatile("cp.async.cg.shared.global [%0], [%1], 16;"
                             :: "r"(dst + off), "l"(g_Whead + off) : "memory");
            }
            asm volatile("cp.async.commit_group;" ::: "memory");
        }

#define HISSUE(c)                                                              \
    {                                                                          \
        const uint32_t dst = sb + HA_OFF + ((c) & 3) * 8192;                   \
        const unsigned char* ga = gA + (size_t)(c) * 16384;                    \
        _Pragma("unroll") for (int i = 0; i < 2; i++) {                        \
            uint32_t off = (uint32_t)(i * 256 + tid) * 16;                     \
            asm volatile("cp.async.cg.shared.global [%0], [%1], 16;"           \
                         :: "r"(dst + off), "l"(ga + off) : "memory");         \
        }                                                                      \
        asm volatile("cp.async.commit_group;" ::: "memory");                   \
    }

        HISSUE(0);
        HISSUE(1);
        HISSUE(2);

        float hacc[2][2][4];
#pragma unroll
        for (int i = 0; i < 2; i++)
#pragma unroll
            for (int j = 0; j < 2; j++)
#pragma unroll
                for (int q = 0; q < 4; q++) hacc[i][j][q] = 0.f;

        const int wm = (w >> 2) * 32;
        const int hwn = (w & 3) * 16;

        for (int c = 0; c < 8; c++) {
            if (c <= 5) {
                asm volatile("cp.async.wait_group 2;" ::: "memory");
            } else if (c == 6) {
                asm volatile("cp.async.wait_group 1;" ::: "memory");
            } else {
                asm volatile("cp.async.wait_group 0;" ::: "memory");
            }
            __syncthreads();

            if (c + 3 < 8) HISSUE(c + 3);

            const uint32_t stA = sb + HA_OFF + (c & 3) * 8192;
            const uint32_t stB = sb + HB_OFF + c * 8192;

#pragma unroll
            for (int ks = 0; ks < 4; ks++) {
                const int kb = ks * 32;
                uint32_t a[2][4], b[4];
#pragma unroll
                for (int mt = 0; mt < 2; mt++) {
                    uint32_t off = (uint32_t)(wm + mt * 16 + arl) * 128 +
                                   (((uint32_t)(kb + acb)) ^ sxor);
                    ldm_x4(a[mt], stA + off);
                }
                {
                    uint32_t off = (uint32_t)(hwn + brl) * 128 +
                                   (((uint32_t)(kb + bkb)) ^ sxor);
                    ldm_x4(b, stB + off);
                }
#pragma unroll
                for (int mt = 0; mt < 2; mt++)
#pragma unroll
                    for (int nt = 0; nt < 2; nt++)
                        mma_f16(hacc[mt][nt], a[mt], &b[nt * 2]);
            }
        }

        __syncthreads();

        float* Lsm = (float*)(smem + HB_OFF);    // [64][66]
#pragma unroll
        for (int mt = 0; mt < 2; mt++)
#pragma unroll
            for (int nt = 0; nt < 2; nt++) {
                const int colL = hwn + nt * 8 + (l & 3) * 2;
                const int r0 = wm + mt * 16 + (l >> 2);
                *(float2*)(Lsm + r0 * 66 + colL) =
                    make_float2(hacc[mt][nt][0], hacc[mt][nt][1]);
                *(float2*)(Lsm + (r0 + 8) * 66 + colL) =
                    make_float2(hacc[mt][nt][2], hacc[mt][nt][3]);
            }
        __syncthreads();

        if (tid < 64) {
            const int agent = mtile * 128 + mhalf * 64 + tid;
            const float* Lr = Lsm + tid * 66;

            float lg[32];
            float mx = -1e30f;
#pragma unroll
            for (int t = 0; t < 32; t++) {
                lg[t] = Lr[t] + bs[t];
                mx = fmaxf(mx, lg[t]);
            }
            float se = 0.f, s1 = 0.f;
#pragma unroll
            for (int t = 0; t < 32; t++) {
                float e = expf(lg[t] - mx);
                se += e;
                s1 += e * lg[t];
            }
            const float lse = mx + logf(se);
            const int act = action[agent];
            const float slp = lg[act & 31] - lse;
            const float ent = lse - s1 / se;
            const float val = Lr[32] + bc[0];

            out[0 * N_AGENTS + agent] = (float)act;
            out[1 * N_AGENTS + agent] = (float)skill[agent];
            out[2 * N_AGENTS + agent] = -2.7725887222397811f;   // -ln(16)
            out[3 * N_AGENTS + agent] = slp;
            out[4 * N_AGENTS + agent] = ent;
            out[5 * N_AGENTS + agent] = val;
        }
    }
}

// ---------------------------------------------------------------------------
// launch
// ---------------------------------------------------------------------------
extern "C" void kernel_launch(void* const* d_in, const int* in_sizes, int n_in,
                              void* d_out, int out_size) {
    (void)in_sizes; (void)n_in; (void)out_size;
    const float* x     = (const float*)d_in[0];
    const float* W_enc = (const float*)d_in[1];
    const float* b_enc = (const float*)d_in[2];
    // d_in[3]=Wm, d_in[4]=bm : dead (selections never returned)
    const float* Ws    = (const float*)d_in[5];
    const float* bs    = (const float*)d_in[6];
    const float* Wc    = (const float*)d_in[7];
    const float* bc    = (const float*)d_in[8];
    const int*   skill = (const int*)d_in[9];
    const int*   act   = (const int*)d_in[10];
    float* out = (float*)d_out;

    unsigned char* dB;
    cudaGetSymbolAddress((void**)&dB, g_Bstage);

    static int cfg_done = 0;
    if (!cfg_done) {
        cudaFuncSetAttribute(enc_gemm_mma, cudaFuncAttributeMaxDynamicSharedMemorySize,
                             ENC_SMEM);
        cfg_done = 1;
    }

    conv_f16_kernel<<<512, 256>>>(W_enc, dB);   // W_enc -> fp16 tiles
    conv_wh_kernel<<<16, 256>>>(Ws, Wc);        // W' staging + zero counters

    enc_gemm_mma<<<2 * MT64, 256, ENC_SMEM>>>(x, b_enc, bs, bc, skill, act, out);
}